// round 7
// baseline (speedup 1.0000x reference)
#include <cuda_runtime.h>

// Half-lattice hop operator, column-split mapping for dense K loads:
//   out = DIAG*psi - 0.5 * sum_mu ( K_fwd[mu] @ psi(fwd nbr) + K_bwd[mu] @ psi(bwd nbr) )
// T=Z=Y=16, X/2=8, D=12 complex. mu<3: periodic roll; mu=3: parity-gated X hop.
//
// Thread layout: 48 threads/site = 12 rows x 4 lanes. Lane q (0..2) handles
// columns 4q..4q+3 of its row (q=3 idle pad for warp alignment). K addresses
// are quad-consecutive across active lanes -> dense warp LDGs (3 lines/request
// instead of 12 with the row-per-thread mapping).

#define DD 12
#define NV (16*16*16*8)            // 32768 sites
#define DIAGC 4.5f
#define KSTRIDE4 (NV*DD*DD/4)      // float4 per (mu) slab = 1179648

__global__ __launch_bounds__(192)
void hop_kernel(const float* __restrict__ psr, const float* __restrict__ psi_,
                const float* __restrict__ Kfr, const float* __restrict__ Kfi,
                const float* __restrict__ Kbr, const float* __restrict__ Kbi,
                float* __restrict__ out)
{
    const int tid = threadIdx.x;          // 0..191
    const int sl  = tid / 48;             // site within block (0..3)
    const int tx  = tid % 48;
    const int i   = tx >> 2;              // row 0..11
    const int q   = tx & 3;               // column quad 0..3 (3 = pad)
    const int site = blockIdx.x * 4 + sl;

    // site bits: x [0:3), y [3:7), z [7:11), t [11:15)
    const int x = site & 7;
    const int y = (site >> 3) & 15;
    const int z = (site >> 7) & 15;
    const int t = (site >> 11) & 15;
    const int r = (t + z + y) & 1;

    // neighbor quad-offsets into psi arrays (site*12 floats = site*3 float4)
    const unsigned nn[8] = {
        ((site & ~(15<<11)) | (((t+1)&15)<<11)) * 3u,   // T fwd
        ((site & ~(15<<11)) | (((t+15)&15)<<11)) * 3u,  // T bwd
        ((site & ~(15<<7))  | (((z+1)&15)<<7)) * 3u,    // Z fwd
        ((site & ~(15<<7))  | (((z+15)&15)<<7)) * 3u,   // Z bwd
        ((site & ~(15<<3))  | (((y+1)&15)<<3)) * 3u,    // Y fwd
        ((site & ~(15<<3))  | (((y+15)&15)<<3)) * 3u,   // Y bwd
        (unsigned)(r ? ((site & ~7) | ((x+1)&7)) : site) * 3u,   // X fwd iff r==1
        (unsigned)(r ? site : ((site & ~7) | ((x+7)&7))) * 3u    // X bwd iff r==0
    };

    const float4* pr4 = reinterpret_cast<const float4*>(psr);
    const float4* pi4 = reinterpret_cast<const float4*>(psi_);
    // this lane's K quad: row i, columns 4q..4q+3
    const unsigned kq = (unsigned)site * 36u + (unsigned)i * 3u + (unsigned)q;

    float hr0 = 0.f, hr1 = 0.f, hi0 = 0.f, hi1 = 0.f;

    if (q < 3) {
#pragma unroll
        for (int s = 0; s < 8; ++s) {
            const int mu = s >> 1;
            const float4 kr = __ldcs(reinterpret_cast<const float4*>((s & 1) ? Kbr : Kfr)
                                     + mu * KSTRIDE4 + kq);
            const float4 ki = __ldcs(reinterpret_cast<const float4*>((s & 1) ? Kbi : Kfi)
                                     + mu * KSTRIDE4 + kq);
            const float4 vr = __ldg(pr4 + nn[s] + q);
            const float4 vi = __ldg(pi4 + nn[s] + q);
            hr0 = fmaf(kr.x, vr.x, hr0); hr0 = fmaf(-ki.x, vi.x, hr0);
            hi0 = fmaf(kr.x, vi.x, hi0); hi0 = fmaf( ki.x, vr.x, hi0);
            hr1 = fmaf(kr.y, vr.y, hr1); hr1 = fmaf(-ki.y, vi.y, hr1);
            hi1 = fmaf(kr.y, vi.y, hi1); hi1 = fmaf( ki.y, vr.y, hi1);
            hr0 = fmaf(kr.z, vr.z, hr0); hr0 = fmaf(-ki.z, vi.z, hr0);
            hi0 = fmaf(kr.z, vi.z, hi0); hi0 = fmaf( ki.z, vr.z, hi0);
            hr1 = fmaf(kr.w, vr.w, hr1); hr1 = fmaf(-ki.w, vi.w, hr1);
            hi1 = fmaf(kr.w, vi.w, hi1); hi1 = fmaf( ki.w, vr.w, hi1);
        }
    }

    // reduce over the 4-lane column group (pad lane contributes 0)
    float hr = hr0 + hr1;
    float hi = hi0 + hi1;
    hr += __shfl_xor_sync(0xffffffffu, hr, 1, 4);
    hr += __shfl_xor_sync(0xffffffffu, hr, 2, 4);
    hi += __shfl_xor_sync(0xffffffffu, hi, 1, 4);
    hi += __shfl_xor_sync(0xffffffffu, hi, 2, 4);

    if (q == 0) {
        const unsigned so = (unsigned)site * DD + (unsigned)i;
        const float pre = __ldg(psr + so);
        const float pim = __ldg(psi_ + so);
        out[so]           = DIAGC * pre - 0.5f * hr;
        out[NV * DD + so] = DIAGC * pim - 0.5f * hi;
    }
}

extern "C" void kernel_launch(void* const* d_in, const int* in_sizes, int n_in,
                              void* d_out, int out_size)
{
    const float* psr = (const float*)d_in[0];
    const float* psi = (const float*)d_in[1];
    const float* Kfr = (const float*)d_in[2];
    const float* Kfi = (const float*)d_in[3];
    const float* Kbr = (const float*)d_in[4];
    const float* Kbi = (const float*)d_in[5];
    float* out = (float*)d_out;

    dim3 block(192);         // 4 sites x 48 threads (12 rows x 4 lanes)
    dim3 grid(NV / 4);       // 8192 blocks
    hop_kernel<<<grid, block>>>(psr, psi, Kfr, Kfi, Kbr, Kbi, out);
}

// round 10
// speedup vs baseline: 1.0826x; 1.0826x over previous
#include <cuda_runtime.h>

// Half-lattice hop operator, psi-neighbors staged in smem once per block:
//   out = DIAG*psi - 0.5 * sum_mu ( K_fwd[mu] @ psi(fwd nbr) + K_bwd[mu] @ psi(bwd nbr) )
// T=Z=Y=16, X/2=8, D=12 complex. mu<3: periodic roll; mu=3: parity-gated X hop.
//
// 12 threads/site (thread = output row), 16 sites/block. The 8 neighbor psi
// vectors per site (12 KB/block) are gathered cooperatively into smem in a
// one-shot prologue; the main loop streams K from DRAM (ldcs) and reads psi
// via LDS broadcast, halving global-load instruction count vs R3.

#define DD 12
#define NV (16*16*16*8)            // 32768 sites
#define DIAGC 4.5f
#define KSTRIDE (NV*DD*DD)         // floats per (mu) slab

// quad offset (float4 units) of neighbor k (k>>1 = mu, k&1 = bwd) of site
__device__ __forceinline__ unsigned nbr_quad(int site, int k)
{
    const int x = site & 7;
    const int y = (site >> 3) & 15;
    const int z = (site >> 7) & 15;
    const int t = (site >> 11) & 15;
    int n;
    switch (k >> 1) {
    case 0: { const int tt = (k & 1) ? (t + 15) & 15 : (t + 1) & 15;
              n = (site & ~(15 << 11)) | (tt << 11); } break;
    case 1: { const int zz = (k & 1) ? (z + 15) & 15 : (z + 1) & 15;
              n = (site & ~(15 << 7)) | (zz << 7); } break;
    case 2: { const int yy = (k & 1) ? (y + 15) & 15 : (y + 1) & 15;
              n = (site & ~(15 << 3)) | (yy << 3); } break;
    default: { const int r = (t + z + y) & 1;   // fwd iff r==1, bwd iff r==0
               if (k & 1) n = r ? site : ((site & ~7) | ((x + 7) & 7));
               else       n = r ? ((site & ~7) | ((x + 1) & 7)) : site; }
    }
    return (unsigned)n * 3u;
}

__global__ __launch_bounds__(192)
void hop_kernel(const float* __restrict__ psr, const float* __restrict__ psi_,
                const float* __restrict__ Kfr, const float* __restrict__ Kfi,
                const float* __restrict__ Kbr, const float* __restrict__ Kbi,
                float* __restrict__ out)
{
    // [site][nbr][quad]: quads 0-2 = psi_re row, 3-5 = psi_im row
    __shared__ float4 sPsi[16][8][6];   // 12288 B

    const int i  = threadIdx.x;         // 0..11 output row
    const int ty = threadIdx.y;         // 0..15 site within block
    const int tid = ty * 12 + i;        // 0..191
    const int site0 = blockIdx.x * 16;
    const int site  = site0 + ty;

    const float4* pr4 = reinterpret_cast<const float4*>(psr);
    const float4* pi4 = reinterpret_cast<const float4*>(psi_);

    // ---- prologue: gather 768 quads of neighbor psi into smem ----
#pragma unroll
    for (int u = 0; u < 4; ++u) {
        const int f   = tid + u * 192;      // 0..767
        const int sl  = f / 48;
        const int rem = f - sl * 48;
        const int k   = rem / 6;
        const int qq  = rem - k * 6;
        const unsigned nq = nbr_quad(site0 + sl, k);
        const float4 v = (qq < 3) ? __ldg(pr4 + nq + qq)
                                  : __ldg(pi4 + nq + (qq - 3));
        sPsi[sl][k][qq] = v;
    }
    __syncthreads();

    // ---- main: stream K, psi from smem ----
    float hr0 = 0.f, hi0 = 0.f, hr1 = 0.f, hi1 = 0.f;
    const unsigned rowoff = (unsigned)site * (DD * DD) + (unsigned)i * DD;

#pragma unroll
    for (int s = 0; s < 8; ++s) {
        const int mu = s >> 1;
        const float* Krb = (s & 1) ? Kbr : Kfr;
        const float* Kib = (s & 1) ? Kbi : Kfi;
        const float4* kr4 = reinterpret_cast<const float4*>(Krb + mu * KSTRIDE + rowoff);
        const float4* ki4 = reinterpret_cast<const float4*>(Kib + mu * KSTRIDE + rowoff);
        const float4* sv = &sPsi[ty][s][0];
#pragma unroll
        for (int c = 0; c < 3; ++c) {
            const float4 kr = __ldcs(kr4 + c);
            const float4 ki = __ldcs(ki4 + c);
            const float4 vr = sv[c];
            const float4 vi = sv[3 + c];
            hr0 = fmaf(kr.x, vr.x, hr0); hr0 = fmaf(-ki.x, vi.x, hr0);
            hi0 = fmaf(kr.x, vi.x, hi0); hi0 = fmaf( ki.x, vr.x, hi0);
            hr1 = fmaf(kr.y, vr.y, hr1); hr1 = fmaf(-ki.y, vi.y, hr1);
            hi1 = fmaf(kr.y, vi.y, hi1); hi1 = fmaf( ki.y, vr.y, hi1);
            hr0 = fmaf(kr.z, vr.z, hr0); hr0 = fmaf(-ki.z, vi.z, hr0);
            hi0 = fmaf(kr.z, vi.z, hi0); hi0 = fmaf( ki.z, vr.z, hi0);
            hr1 = fmaf(kr.w, vr.w, hr1); hr1 = fmaf(-ki.w, vi.w, hr1);
            hi1 = fmaf(kr.w, vi.w, hi1); hi1 = fmaf( ki.w, vr.w, hi1);
        }
    }

    const unsigned so = (unsigned)site * DD + (unsigned)i;
    const float pre = __ldg(psr + so);
    const float pim = __ldg(psi_ + so);
    out[so]           = DIAGC * pre - 0.5f * (hr0 + hr1);
    out[NV * DD + so] = DIAGC * pim - 0.5f * (hi0 + hi1);
}

extern "C" void kernel_launch(void* const* d_in, const int* in_sizes, int n_in,
                              void* d_out, int out_size)
{
    const float* psr = (const float*)d_in[0];
    const float* psi = (const float*)d_in[1];
    const float* Kfr = (const float*)d_in[2];
    const float* Kfi = (const float*)d_in[3];
    const float* Kbr = (const float*)d_in[4];
    const float* Kbi = (const float*)d_in[5];
    float* out = (float*)d_out;

    dim3 block(12, 16);      // 12 rows x 16 sites = 192 threads
    dim3 grid(NV / 16);      // 2048 blocks
    hop_kernel<<<grid, block>>>(psr, psi, Kfr, Kfi, Kbr, Kbi, out);
}

// round 11
// speedup vs baseline: 1.1429x; 1.0556x over previous
#include <cuda_runtime.h>

// Half-lattice hop operator (R3 body, 8-sites/96-thread blocks):
//   out = DIAG*psi - 0.5 * sum_mu ( K_fwd[mu] @ psi(fwd nbr) + K_bwd[mu] @ psi(bwd nbr) )
// T=Z=Y=16, X/2=8, D=12 complex. mu<3: periodic roll on t/z/y; mu=3: parity-gated X hop.
// Thread = (site, output row). Smaller blocks raise regs-limited occupancy
// (11 blocks/SM x 3 warps = 33 warps vs 30) and smooth the drain tail.

#define DD 12
#define NV (16*16*16*8)   // 32768 sites
#define DIAGC 4.5f
#define KSTRIDE (NV * DD * DD)   // 4718592 floats, fits u32

__device__ __forceinline__ void cmatvec_row(
    const float* __restrict__ Krb, const float* __restrict__ Kib, unsigned ko,
    const float* __restrict__ prb, const float* __restrict__ pib, unsigned po,
    float& hr0, float& hi0, float& hr1, float& hi1)
{
    const float4* kr4 = reinterpret_cast<const float4*>(Krb + ko);
    const float4* ki4 = reinterpret_cast<const float4*>(Kib + ko);
    const float4* pr4 = reinterpret_cast<const float4*>(prb + po);
    const float4* pi4 = reinterpret_cast<const float4*>(pib + po);
#pragma unroll
    for (int c = 0; c < 3; ++c) {
        float4 kr = __ldg(kr4 + c);
        float4 ki = __ldg(ki4 + c);
        float4 vr = __ldg(pr4 + c);
        float4 vi = __ldg(pi4 + c);
        hr0 = fmaf(kr.x, vr.x, hr0); hr0 = fmaf(-ki.x, vi.x, hr0);
        hi0 = fmaf(kr.x, vi.x, hi0); hi0 = fmaf( ki.x, vr.x, hi0);
        hr1 = fmaf(kr.y, vr.y, hr1); hr1 = fmaf(-ki.y, vi.y, hr1);
        hi1 = fmaf(kr.y, vi.y, hi1); hi1 = fmaf( ki.y, vr.y, hi1);
        hr0 = fmaf(kr.z, vr.z, hr0); hr0 = fmaf(-ki.z, vi.z, hr0);
        hi0 = fmaf(kr.z, vi.z, hi0); hi0 = fmaf( ki.z, vr.z, hi0);
        hr1 = fmaf(kr.w, vr.w, hr1); hr1 = fmaf(-ki.w, vi.w, hr1);
        hi1 = fmaf(kr.w, vi.w, hi1); hi1 = fmaf( ki.w, vr.w, hi1);
    }
}

__global__ __launch_bounds__(96)
void hop_kernel(const float* __restrict__ psr, const float* __restrict__ psi,
                const float* __restrict__ Kfr, const float* __restrict__ Kfi,
                const float* __restrict__ Kbr, const float* __restrict__ Kbi,
                float* __restrict__ out)
{
    const int site = blockIdx.x * 8 + threadIdx.y;
    const int i = threadIdx.x;   // 0..11, output row

    // site bits: x [0:3), y [3:7), z [7:11), t [11:15)
    const int x = site & 7;
    const int y = (site >> 3) & 15;
    const int z = (site >> 7) & 15;
    const int t = (site >> 11) & 15;

    const int nTf = (site & ~(15 << 11)) | (((t + 1) & 15) << 11);
    const int nTb = (site & ~(15 << 11)) | (((t + 15) & 15) << 11);
    const int nZf = (site & ~(15 << 7))  | (((z + 1) & 15) << 7);
    const int nZb = (site & ~(15 << 7))  | (((z + 15) & 15) << 7);
    const int nYf = (site & ~(15 << 3))  | (((y + 1) & 15) << 3);
    const int nYb = (site & ~(15 << 3))  | (((y + 15) & 15) << 3);
    const int r = (t + z + y) & 1;
    const int nXf = r ? ((site & ~7) | ((x + 1) & 7)) : site;    // fwd hop iff r==1
    const int nXb = r ? site : ((site & ~7) | ((x + 7) & 7));    // bwd hop iff r==0

    const unsigned nf[4] = {(unsigned)nTf * DD, (unsigned)nZf * DD,
                            (unsigned)nYf * DD, (unsigned)nXf * DD};
    const unsigned nb[4] = {(unsigned)nTb * DD, (unsigned)nZb * DD,
                            (unsigned)nYb * DD, (unsigned)nXb * DD};

    float hr0 = 0.f, hi0 = 0.f, hr1 = 0.f, hi1 = 0.f;
    const unsigned rowoff = (unsigned)site * (DD * DD) + (unsigned)i * DD;

#pragma unroll
    for (int mu = 0; mu < 4; ++mu) {
        const unsigned ko = (unsigned)mu * KSTRIDE + rowoff;
        cmatvec_row(Kfr, Kfi, ko, psr, psi, nf[mu], hr0, hi0, hr1, hi1);
        cmatvec_row(Kbr, Kbi, ko, psr, psi, nb[mu], hr0, hi0, hr1, hi1);
    }

    const unsigned so = (unsigned)site * DD + (unsigned)i;
    const float pre = __ldg(psr + so);
    const float pim = __ldg(psi + so);
    out[so]           = DIAGC * pre - 0.5f * (hr0 + hr1);
    out[NV * DD + so] = DIAGC * pim - 0.5f * (hi0 + hi1);
}

extern "C" void kernel_launch(void* const* d_in, const int* in_sizes, int n_in,
                              void* d_out, int out_size)
{
    const float* psr = (const float*)d_in[0];
    const float* psi = (const float*)d_in[1];
    const float* Kfr = (const float*)d_in[2];
    const float* Kfi = (const float*)d_in[3];
    const float* Kbr = (const float*)d_in[4];
    const float* Kbi = (const float*)d_in[5];
    float* out = (float*)d_out;

    dim3 block(12, 8);       // 12 rows x 8 sites = 96 threads
    dim3 grid(NV / 8);       // 4096 blocks
    hop_kernel<<<grid, block>>>(psr, psi, Kfr, Kfi, Kbr, Kbi, out);
}